// round 13
// baseline (speedup 1.0000x reference)
#include <cuda_runtime.h>
#include <cstddef>
#include <cstdint>

// CapsuleLayer dynamic routing, recompute-u_hat strategy + packed f32x2 math.
// x: [64, 2048, 8], W: [32, 2048, 16, 8], out v: [64, 32, 16] (fp32)
//
// Math restructure:
//   b starts at 0 and accumulates linearly => logits at iter k are u_hat . (v1+..+vk)
//   pass0: S1 = sum_n u_hat            (c uniform = 1/32 folded into squash)
//   pass1: c = softmax_j(u_hat . v1)        -> S2
//   pass2: c = softmax_j(u_hat . (v1+v2))   -> S3 -> v3 = output
//
// R13: break the register-occupancy lock. At 128 regs x 16 warps the RF is
// full -> occupancy pinned at 25%, all scheduling tricks neutral (R7-R12).
// Re-shard: 512-thread CTAs, 2 b's/thread (half the per-thread state),
// __launch_bounds__(512,2) -> 64 regs, 32 warps/SM (full RF at 64 regs).
// Reverts R12's softmax pipelining (regression). Keeps R11 pipeline schedule,
// xdup f32x2 operands, fused inter-pass squash, 5 launches.

#define B_DIM 64
#define N_DIM 2048
#define I_DIM 8
#define J_DIM 32
#define D_DIM 16

#define NC 32              // n's per block
#define BC 8               // b's per block
#define NTHREADS 512
#define WS_STRIDE 132      // floats per W row in smem (128 + 4 pad)
#define WBUF_FLOATS (J_DIM * WS_STRIDE)       // 4224 floats per stage
#define XD_ULLS (BC * NC * I_DIM)             // 2048 ull (x duplicated pairs)
#define TB_FLOATS (16 * J_DIM * 2)            // 1024 ([warp][j] float2)
#define SMEM_FLOATS (4 * WBUF_FLOATS + 2 * XD_ULLS + TB_FLOATS)
#define SMEM_BYTES (SMEM_FLOATS * 4)          // 88064 B -> 2 CTAs/SM

__device__ float g_Wt[(size_t)J_DIM * N_DIM * 128];   // transposed W, [j][n][i][d]
__device__ float g_S[3][B_DIM * J_DIM * D_DIM];       // routing-pass accumulators

typedef unsigned long long ull;

__device__ __forceinline__ ull f2_fma(ull a, ull b, ull c) {
    ull d; asm("fma.rn.f32x2 %0, %1, %2, %3;" : "=l"(d) : "l"(a), "l"(b), "l"(c)); return d;
}
__device__ __forceinline__ ull f2_mul(ull a, ull b) {
    ull d; asm("mul.rn.f32x2 %0, %1, %2;" : "=l"(d) : "l"(a), "l"(b)); return d;
}
__device__ __forceinline__ ull f2_add(ull a, ull b) {
    ull d; asm("add.rn.f32x2 %0, %1, %2;" : "=l"(d) : "l"(a), "l"(b)); return d;
}
__device__ __forceinline__ ull f2_dup(float x) {
    ull d; asm("mov.b64 %0, {%1, %1};" : "=l"(d) : "f"(x)); return d;
}
__device__ __forceinline__ ull f2_pack(float lo, float hi) {
    ull d; asm("mov.b64 %0, {%1, %2};" : "=l"(d) : "f"(lo), "f"(hi)); return d;
}
__device__ __forceinline__ void f2_unpack(ull v, float& lo, float& hi) {
    asm("mov.b64 {%0, %1}, %2;" : "=f"(lo), "=f"(hi) : "l"(v));
}
__device__ __forceinline__ float f2_hsum(ull v) {
    float lo, hi; f2_unpack(v, lo, hi); return lo + hi;
}

__device__ __forceinline__ void cp16(void* dst_smem, const void* src) {
    uint32_t d = (uint32_t)__cvta_generic_to_shared(dst_smem);
    asm volatile("cp.async.cg.shared.global [%0], [%1], 16;" :: "r"(d), "l"(src));
}
__device__ __forceinline__ void cp_commit() { asm volatile("cp.async.commit_group;"); }
__device__ __forceinline__ void cp_wait0()  { asm volatile("cp.async.wait_group 0;"); }

// Transpose W[j][n][d][i] -> g_Wt[j][n][i][d], and zero g_S (replaces init kernel).
__global__ void transform_kernel(const float* __restrict__ W) {
    __shared__ float s[8][WS_STRIDE];
    const int t = threadIdx.x;
    const int gid = blockIdx.x * 256 + t;
    if (gid < 3 * B_DIM * J_DIM * D_DIM) ((float*)g_S)[gid] = 0.0f;

    const int r = t >> 5;
    const int l = t & 31;
    const size_t row = (size_t)blockIdx.x * 8 + r;

    const float4* src = reinterpret_cast<const float4*>(W + row * 128);
    *reinterpret_cast<float4*>(&s[r][l * 4]) = __ldg(src + l);
    __syncthreads();

    const int i = l >> 2, dq = l & 3;
    float4 o;
    o.x = s[r][(dq * 4 + 0) * I_DIM + i];
    o.y = s[r][(dq * 4 + 1) * I_DIM + i];
    o.z = s[r][(dq * 4 + 2) * I_DIM + i];
    o.w = s[r][(dq * 4 + 3) * I_DIM + i];
    *reinterpret_cast<float4*>(&g_Wt[row * 128 + l * 4]) = o;
}

// squash helper: given raw S row (4 float4s) and scale, return normalized quarter dq.
__device__ __forceinline__ float4 squash_quarter(const float4* Sp, float scale, int dq) {
    float4 r0 = Sp[0], r1 = Sp[1], r2 = Sp[2], r3 = Sp[3];
    r0.x *= scale; r0.y *= scale; r0.z *= scale; r0.w *= scale;
    r1.x *= scale; r1.y *= scale; r1.z *= scale; r1.w *= scale;
    r2.x *= scale; r2.y *= scale; r2.z *= scale; r2.w *= scale;
    r3.x *= scale; r3.y *= scale; r3.z *= scale; r3.w *= scale;
    float ssq = r0.x*r0.x + r0.y*r0.y + r0.z*r0.z + r0.w*r0.w
              + r1.x*r1.x + r1.y*r1.y + r1.z*r1.z + r1.w*r1.w
              + r2.x*r2.x + r2.y*r2.y + r2.z*r2.z + r2.w*r2.w
              + r3.x*r3.x + r3.y*r3.y + r3.z*r3.z + r3.w*r3.w;
    float inv = rsqrtf(ssq + 1e-7f);
    float4 q = (dq == 0) ? r0 : (dq == 1) ? r1 : (dq == 2) ? r2 : r3;
    q.x *= inv; q.y *= inv; q.z *= inv; q.w *= inv;
    return q;
}

// Block: 512 threads. lane = j (0..31). warp w (0..15): dq = w&3, rep = w>>2 (0..3).
// Each thread handles 2 b's (bbase + rep*2 + bs) x 4 d's (dq*4..dq*4+3) as f32x2 pairs.
// 4-stage cp.async W pipeline, 2 n per barrier, R11-proven schedule.
// For pass>=1 each block recomputes its V-slice from g_S (fused squash).
__global__ __launch_bounds__(NTHREADS, 2) void pass_kernel(
    const float* __restrict__ x, int pass)
{
    extern __shared__ float smem[];
    float*  Wb   = smem;                               // 4 stages x 4224 floats
    ull*    xdup = reinterpret_cast<ull*>(smem + 4 * WBUF_FLOATS);  // [b][nn][i] dup pairs
    float2* tbf  = reinterpret_cast<float2*>(xdup + XD_ULLS);       // [16][32] float2

    const int t    = threadIdx.x;
    const int j    = t & 31;
    const int warp = t >> 5;
    const int dq   = warp & 3;              // d-quarter
    const int rep  = warp >> 2;             // 0..3

    const int bbase  = blockIdx.y * BC;
    const int n_base = blockIdx.x * NC;

    // W staging: thread stages row sj (0..31), 2 chunks at sp*4 and sp*4+64 floats
    const int sj = t >> 4;
    const int sp = t & 15;
    const float* wsrc_base = g_Wt + (size_t)sj * N_DIM * 128 + (size_t)n_base * 128 + sp * 4;
    float* wdst_base = Wb + sj * WS_STRIDE + sp * 4;

    // ---- prologue: W stages 0,1 via cp.async (group 0) ----
    #pragma unroll
    for (int st = 0; st < 2; ++st) {
        cp16(wdst_base + st * WBUF_FLOATS,      wsrc_base + (size_t)st * 128);
        cp16(wdst_base + st * WBUF_FLOATS + 64, wsrc_base + (size_t)st * 128 + 64);
    }
    cp_commit();

    // ---- x tile: load + duplicate into smem pairs (overlaps cp.async) ----
    {
        int b_off = t >> 6;                  // 512 float4s, one per thread
        int rem   = t & 63;
        float4 a = __ldg(reinterpret_cast<const float4*>(
            x + ((size_t)(bbase + b_off) * N_DIM + n_base) * I_DIM) + rem);
        ull* dst = xdup + b_off * (NC * I_DIM) + rem * 4;
        dst[0] = f2_dup(a.x);
        dst[1] = f2_dup(a.y);
        dst[2] = f2_dup(a.z);
        dst[3] = f2_dup(a.w);
    }

    // ---- fused squash: recompute V-slice from g_S ----
    ull V2[2][2];
    if (pass != 0) {
        #pragma unroll
        for (int bs = 0; bs < 2; ++bs) {
            const size_t row = (size_t)(bbase + rep * 2 + bs) * J_DIM + j;
            float4 q = squash_quarter(
                reinterpret_cast<const float4*>(&g_S[0][row * D_DIM]),
                1.0f / 32.0f, dq);
            if (pass == 2) {
                float4 q2 = squash_quarter(
                    reinterpret_cast<const float4*>(&g_S[1][row * D_DIM]),
                    1.0f, dq);
                q.x += q2.x; q.y += q2.y; q.z += q2.z; q.w += q2.w;
            }
            V2[bs][0] = f2_pack(q.x, q.y);
            V2[bs][1] = f2_pack(q.z, q.w);
        }
    }

    ull acc2[2][2];
    #pragma unroll
    for (int bs = 0; bs < 2; ++bs) { acc2[bs][0] = 0ull; acc2[bs][1] = 0ull; }

    // x tile written by this block's own threads -> one block barrier
    __syncthreads();

    // 16 iterations, 2 n each. At iter it: wait all -> sync -> commit stages
    // 2it+2, 2it+3 (target buffers were last read at iter it-1; compute buffers
    // differ by 2 mod 4 -> disjoint). R11-proven schedule.
    for (int it = 0; it < NC / 2; ++it) {
        cp_wait0();
        __syncthreads();

        if (2 * it + 2 < NC) {
            #pragma unroll
            for (int h = 0; h < 2; ++h) {
                const int st = 2 * it + 2 + h;
                float* dst = wdst_base + (st & 3) * WBUF_FLOATS;
                const float* src = wsrc_base + (size_t)st * 128;
                cp16(dst,      src);
                cp16(dst + 64, src + 64);
            }
        }
        cp_commit();

        #pragma unroll
        for (int h = 0; h < 2; ++h) {
            const int nn = 2 * it + h;

            // u_hat (packed d-pairs): W from stage buffer, x from dup'd smem
            const float* Wc = Wb + (nn & 3) * WBUF_FLOATS + j * WS_STRIDE + dq * 4;
            const ull* xr = xdup + (rep * 2) * (NC * I_DIM) + nn * I_DIM;
            ull u2[2][2];
            {
                ulonglong2 wv = *reinterpret_cast<const ulonglong2*>(Wc);
                #pragma unroll
                for (int bs = 0; bs < 2; ++bs) {
                    ull xd = xr[bs * (NC * I_DIM)];
                    u2[bs][0] = f2_mul(wv.x, xd);
                    u2[bs][1] = f2_mul(wv.y, xd);
                }
            }
            #pragma unroll
            for (int i = 1; i < 8; ++i) {
                ulonglong2 wv = *reinterpret_cast<const ulonglong2*>(Wc + i * 16);
                #pragma unroll
                for (int bs = 0; bs < 2; ++bs) {
                    ull xd = xr[bs * (NC * I_DIM) + i];
                    u2[bs][0] = f2_fma(wv.x, xd, u2[bs][0]);
                    u2[bs][1] = f2_fma(wv.y, xd, u2[bs][1]);
                }
            }

            if (pass != 0) {
                // logit partials over this d-quarter, packed exchange (STS.64)
                float2 part;
                part.x = f2_hsum(f2_fma(u2[0][0], V2[0][0], f2_mul(u2[0][1], V2[0][1])));
                part.y = f2_hsum(f2_fma(u2[1][0], V2[1][0], f2_mul(u2[1][1], V2[1][1])));
                tbf[warp * 32 + j] = part;
                asm volatile("bar.sync %0, 128;" :: "r"(1 + rep) : "memory");
                const int wg = rep * 4;
                float2 a0 = tbf[(wg + 0) * 32 + j];
                float2 a1 = tbf[(wg + 1) * 32 + j];
                float2 a2 = tbf[(wg + 2) * 32 + j];
                float2 a3 = tbf[(wg + 3) * 32 + j];
                // logits are O(1): softmax without max-subtraction is safe here
                float e0 = __expf((a0.x + a1.x) + (a2.x + a3.x));
                float e1 = __expf((a0.y + a1.y) + (a2.y + a3.y));
                // 2 interleaved butterflies: independent chains pipeline
                float z0 = e0, z1 = e1;
                #pragma unroll
                for (int o = 16; o; o >>= 1) {
                    z0 += __shfl_xor_sync(0xffffffffu, z0, o);
                    z1 += __shfl_xor_sync(0xffffffffu, z1, o);
                }
                ull c2;
                c2 = f2_dup(__fdividef(e0, z0));
                acc2[0][0] = f2_fma(c2, u2[0][0], acc2[0][0]);
                acc2[0][1] = f2_fma(c2, u2[0][1], acc2[0][1]);
                c2 = f2_dup(__fdividef(e1, z1));
                acc2[1][0] = f2_fma(c2, u2[1][0], acc2[1][0]);
                acc2[1][1] = f2_fma(c2, u2[1][1], acc2[1][1]);
            } else {
                #pragma unroll
                for (int bs = 0; bs < 2; ++bs) {
                    acc2[bs][0] = f2_add(acc2[bs][0], u2[bs][0]);
                    acc2[bs][1] = f2_add(acc2[bs][1], u2[bs][1]);
                }
            }
        }
    }

    float* S = g_S[pass];
    #pragma unroll
    for (int bs = 0; bs < 2; ++bs) {
        float* dst = &S[((size_t)(bbase + rep * 2 + bs) * J_DIM + j) * D_DIM + dq * 4];
        float a, b, c, d;
        f2_unpack(acc2[bs][0], a, b);
        f2_unpack(acc2[bs][1], c, d);
        atomicAdd(dst + 0, a);
        atomicAdd(dst + 1, b);
        atomicAdd(dst + 2, c);
        atomicAdd(dst + 3, d);
    }
}

// final squash only: out = squash(S2). idx = (b*32 + j).
__global__ void squash_final_kernel(float* __restrict__ out) {
    int idx = blockIdx.x * blockDim.x + threadIdx.x;
    if (idx >= B_DIM * J_DIM) return;
    const float* S = g_S[2];
    float s[D_DIM];
    float ssq = 0.0f;
#pragma unroll
    for (int d = 0; d < D_DIM; ++d) {
        float v = S[idx * D_DIM + d];
        s[d] = v;
        ssq = fmaf(v, v, ssq);
    }
    float inv = rsqrtf(ssq + 1e-7f);
#pragma unroll
    for (int d = 0; d < D_DIM; ++d) out[idx * D_DIM + d] = s[d] * inv;
}

extern "C" void kernel_launch(void* const* d_in, const int* in_sizes, int n_in,
                              void* d_out, int out_size) {
    const float* x = (const float*)d_in[0];
    const float* W = (const float*)d_in[1];
    // robust to input ordering: x has 64*2048*8 = 1048576 elements
    if (in_sizes[0] != B_DIM * N_DIM * I_DIM) {
        x = (const float*)d_in[1];
        W = (const float*)d_in[0];
    }
    float* out = (float*)d_out;

    cudaFuncSetAttribute(pass_kernel,
                         cudaFuncAttributeMaxDynamicSharedMemorySize, SMEM_BYTES);

    dim3 grid(N_DIM / NC, B_DIM / BC);   // (64, 8) = 512 blocks

    transform_kernel<<<(J_DIM * N_DIM) / 8, 256>>>(W);   // also zeroes g_S
    pass_kernel<<<grid, NTHREADS, SMEM_BYTES>>>(x, 0);
    pass_kernel<<<grid, NTHREADS, SMEM_BYTES>>>(x, 1);   // squash(S0) fused in prologue
    pass_kernel<<<grid, NTHREADS, SMEM_BYTES>>>(x, 2);   // squash(S0)+squash(S1) fused
    squash_final_kernel<<<8, 256>>>(out);
}

// round 14
// speedup vs baseline: 1.2049x; 1.2049x over previous
#include <cuda_runtime.h>
#include <cstddef>
#include <cstdint>

// CapsuleLayer dynamic routing, recompute-u_hat strategy + packed f32x2 math.
// x: [64, 2048, 8], W: [32, 2048, 16, 8], out v: [64, 32, 16] (fp32)
//
// Math restructure:
//   b starts at 0 and accumulates linearly => logits at iter k are u_hat . (v1+..+vk)
//   pass0: S1 = sum_n u_hat            (c uniform = 1/32 folded into squash)
//   pass1: c = softmax_j(u_hat . v1)        -> S2
//   pass2: c = softmax_j(u_hat . (v1+v2))   -> S3 -> v3 = output
//
// R14: 2n-batched softmax tail. R13 proved occupancy is not the binder (2x
// warps -> worse); the binder is the per-n phase-locked exchange/exp/shfl
// chain. This round: back to R11's 256-thread shape, hold u2 for both n of
// each pipeline window (+16 regs), pay by moving V to a conflict-free smem
// tile Vs[p][b][j] (-16 regs), ONE named barrier per 2n, batched 8-chain
// softmax tail. Squash computed once per (b,j) row in the prologue.

#define B_DIM 64
#define N_DIM 2048
#define I_DIM 8
#define J_DIM 32
#define D_DIM 16

#define NC 32              // n's per block
#define BC 8               // b's per block
#define WS_STRIDE 132      // floats per W row in smem (128 + 4 pad)
#define WBUF_FLOATS (J_DIM * WS_STRIDE)       // 4224 floats per stage
#define XT_FLOATS (BC * NC * I_DIM)           // 2048
#define TB_FLOATS (2 * 8 * J_DIM * 4)         // 2048 ([h][warp][j] float4)
#define VS_ULLS (8 * BC * J_DIM)              // 2048 ([p][b][j] ull)
#define SMEM_FLOATS (4 * WBUF_FLOATS + XT_FLOATS + TB_FLOATS + 2 * VS_ULLS)
#define SMEM_BYTES (SMEM_FLOATS * 4)          // 100352 B -> 2 CTAs/SM

__device__ float g_Wt[(size_t)J_DIM * N_DIM * 128];   // transposed W, [j][n][i][d]
__device__ float g_S[3][B_DIM * J_DIM * D_DIM];       // routing-pass accumulators

typedef unsigned long long ull;

__device__ __forceinline__ ull f2_fma(ull a, ull b, ull c) {
    ull d; asm("fma.rn.f32x2 %0, %1, %2, %3;" : "=l"(d) : "l"(a), "l"(b), "l"(c)); return d;
}
__device__ __forceinline__ ull f2_mul(ull a, ull b) {
    ull d; asm("mul.rn.f32x2 %0, %1, %2;" : "=l"(d) : "l"(a), "l"(b)); return d;
}
__device__ __forceinline__ ull f2_add(ull a, ull b) {
    ull d; asm("add.rn.f32x2 %0, %1, %2;" : "=l"(d) : "l"(a), "l"(b)); return d;
}
__device__ __forceinline__ ull f2_dup(float x) {
    ull d; asm("mov.b64 %0, {%1, %1};" : "=l"(d) : "f"(x)); return d;
}
__device__ __forceinline__ ull f2_pack(float lo, float hi) {
    ull d; asm("mov.b64 %0, {%1, %2};" : "=l"(d) : "f"(lo), "f"(hi)); return d;
}
__device__ __forceinline__ void f2_unpack(ull v, float& lo, float& hi) {
    asm("mov.b64 {%0, %1}, %2;" : "=f"(lo), "=f"(hi) : "l"(v));
}
__device__ __forceinline__ float f2_hsum(ull v) {
    float lo, hi; f2_unpack(v, lo, hi); return lo + hi;
}

__device__ __forceinline__ void cp16(void* dst_smem, const void* src) {
    uint32_t d = (uint32_t)__cvta_generic_to_shared(dst_smem);
    asm volatile("cp.async.cg.shared.global [%0], [%1], 16;" :: "r"(d), "l"(src));
}
__device__ __forceinline__ void cp_commit() { asm volatile("cp.async.commit_group;"); }
__device__ __forceinline__ void cp_wait0()  { asm volatile("cp.async.wait_group 0;"); }

// Transpose W[j][n][d][i] -> g_Wt[j][n][i][d], and zero g_S (replaces init kernel).
__global__ void transform_kernel(const float* __restrict__ W) {
    __shared__ float s[8][WS_STRIDE];
    const int t = threadIdx.x;
    const int gid = blockIdx.x * 256 + t;
    if (gid < 3 * B_DIM * J_DIM * D_DIM) ((float*)g_S)[gid] = 0.0f;

    const int r = t >> 5;
    const int l = t & 31;
    const size_t row = (size_t)blockIdx.x * 8 + r;

    const float4* src = reinterpret_cast<const float4*>(W + row * 128);
    *reinterpret_cast<float4*>(&s[r][l * 4]) = __ldg(src + l);
    __syncthreads();

    const int i = l >> 2, dq = l & 3;
    float4 o;
    o.x = s[r][(dq * 4 + 0) * I_DIM + i];
    o.y = s[r][(dq * 4 + 1) * I_DIM + i];
    o.z = s[r][(dq * 4 + 2) * I_DIM + i];
    o.w = s[r][(dq * 4 + 3) * I_DIM + i];
    *reinterpret_cast<float4*>(&g_Wt[row * 128 + l * 4]) = o;
}

// accumulate scaled S row into s[16] and return sum of squares contribution
__device__ __forceinline__ void squash_row(const float4* Sp, float scale, float (&s)[16]) {
    float4 r0 = Sp[0], r1 = Sp[1], r2 = Sp[2], r3 = Sp[3];
    s[0]=r0.x*scale; s[1]=r0.y*scale; s[2]=r0.z*scale; s[3]=r0.w*scale;
    s[4]=r1.x*scale; s[5]=r1.y*scale; s[6]=r1.z*scale; s[7]=r1.w*scale;
    s[8]=r2.x*scale; s[9]=r2.y*scale; s[10]=r2.z*scale; s[11]=r2.w*scale;
    s[12]=r3.x*scale; s[13]=r3.y*scale; s[14]=r3.z*scale; s[15]=r3.w*scale;
    float ssq = 0.0f;
    #pragma unroll
    for (int d = 0; d < 16; ++d) ssq = fmaf(s[d], s[d], ssq);
    float inv = rsqrtf(ssq + 1e-7f);
    #pragma unroll
    for (int d = 0; d < 16; ++d) s[d] *= inv;
}

// u_hat for one n: 4 b's x 4 d's as f2 pairs. W from stage buffer, x from xtile.
__device__ __forceinline__ void compute_u(const float* __restrict__ Wc,
                                          const float* __restrict__ xtile,
                                          int rep, int nn, ull (&u2)[4][2]) {
    float xs[4][8];
    #pragma unroll
    for (int bs = 0; bs < 4; ++bs) {
        const float4* xp = reinterpret_cast<const float4*>(
            &xtile[(rep * 4 + bs) * (NC * I_DIM) + nn * I_DIM]);
        float4 a = xp[0], b = xp[1];
        xs[bs][0] = a.x; xs[bs][1] = a.y; xs[bs][2] = a.z; xs[bs][3] = a.w;
        xs[bs][4] = b.x; xs[bs][5] = b.y; xs[bs][6] = b.z; xs[bs][7] = b.w;
    }
    {
        ulonglong2 wv = *reinterpret_cast<const ulonglong2*>(Wc);
        #pragma unroll
        for (int bs = 0; bs < 4; ++bs) {
            ull xd = f2_dup(xs[bs][0]);
            u2[bs][0] = f2_mul(wv.x, xd);
            u2[bs][1] = f2_mul(wv.y, xd);
        }
    }
    #pragma unroll
    for (int i = 1; i < 8; ++i) {
        ulonglong2 wv = *reinterpret_cast<const ulonglong2*>(Wc + i * 16);
        #pragma unroll
        for (int bs = 0; bs < 4; ++bs) {
            ull xd = f2_dup(xs[bs][i]);
            u2[bs][0] = f2_fma(wv.x, xd, u2[bs][0]);
            u2[bs][1] = f2_fma(wv.y, xd, u2[bs][1]);
        }
    }
}

// Block: 256 threads. lane = j. warp w: dq = w&3, rep = w>>2 (0..1).
// Thread: 4 b's (bbase + rep*4 + bs) x 4 d's (dq*4..dq*4+3) as f32x2 pairs.
// 4-stage cp.async W pipeline (R11-proven schedule), 2 n per window.
// ONE named barrier per 2n: both n's logit partials exchanged together,
// softmax tail runs 8 interleaved chains. V lives in smem tile Vs[p][b][j].
__global__ __launch_bounds__(256, 2) void pass_kernel(
    const float* __restrict__ x, int pass)
{
    extern __shared__ float smem[];
    float*  Wb    = smem;                              // 4 stages x 4224 floats
    float*  xtile = smem + 4 * WBUF_FLOATS;            // [b][nn][i] : 2048 floats
    float4* tbf   = reinterpret_cast<float4*>(xtile + XT_FLOATS);       // [2][8][32]
    ull*    Vs    = reinterpret_cast<ull*>(xtile + XT_FLOATS + TB_FLOATS); // [8][8][32]

    const int t    = threadIdx.x;
    const int j    = t & 31;
    const int warp = t >> 5;
    const int dq   = warp & 3;              // d-quarter
    const int rep  = warp >> 2;             // 0..1
    const int wg   = rep * 4;

    const int bbase  = blockIdx.y * BC;
    const int n_base = blockIdx.x * NC;

    // W staging: thread stages row sj, chunks sp*4 + k*32 (conflict-free)
    const int sj = t >> 3;
    const int sp = t & 7;
    const float* wsrc_base = g_Wt + (size_t)sj * N_DIM * 128 + (size_t)n_base * 128 + sp * 4;
    float* wdst_base = Wb + sj * WS_STRIDE + sp * 4;

    // ---- prologue: group 0 = x tile + W stages 0,1 ----
    #pragma unroll
    for (int r = 0; r < 2; ++r) {
        int f = t + r * 256;
        int b_off = f >> 6;
        int rem   = f & 63;
        cp16(&xtile[b_off * (NC * I_DIM) + rem * 4],
             x + ((size_t)(bbase + b_off) * N_DIM + n_base) * I_DIM + rem * 4);
    }
    #pragma unroll
    for (int st = 0; st < 2; ++st)
        #pragma unroll
        for (int k = 0; k < 4; ++k)
            cp16(wdst_base + st * WBUF_FLOATS + k * 32,
                 wsrc_base + (size_t)st * 128 + k * 32);
    cp_commit();

    // ---- fill Vs[p][b][j]: one (b,j) row per thread, squash computed once ----
    if (pass != 0) {
        const int bloc = t >> 5;             // 0..7
        const int jj   = t & 31;
        const size_t row = (size_t)(bbase + bloc) * J_DIM + jj;
        float s[16];
        squash_row(reinterpret_cast<const float4*>(&g_S[0][row * D_DIM]),
                   1.0f / 32.0f, s);
        if (pass == 2) {
            float s2[16];
            squash_row(reinterpret_cast<const float4*>(&g_S[1][row * D_DIM]),
                       1.0f, s2);
            #pragma unroll
            for (int d = 0; d < 16; ++d) s[d] += s2[d];
        }
        #pragma unroll
        for (int p = 0; p < 8; ++p)
            Vs[(p * BC + bloc) * J_DIM + jj] = f2_pack(s[2 * p], s[2 * p + 1]);
    }
    // Vs + xtile become visible at the first window's __syncthreads.

    ull acc2[4][2];
    #pragma unroll
    for (int bs = 0; bs < 4; ++bs) { acc2[bs][0] = 0ull; acc2[bs][1] = 0ull; }

    // 16 windows, 2 n each. R11-proven schedule: wait all -> sync -> commit
    // stages 2it+2, 2it+3 (their buffers were last read at window it-1).
    for (int it = 0; it < NC / 2; ++it) {
        cp_wait0();
        __syncthreads();

        if (2 * it + 2 < NC) {
            #pragma unroll
            for (int h = 0; h < 2; ++h) {
                const int st = 2 * it + 2 + h;
                float* dst = wdst_base + (st & 3) * WBUF_FLOATS;
                const float* src = wsrc_base + (size_t)st * 128;
                #pragma unroll
                for (int k = 0; k < 4; ++k) cp16(dst + k * 32, src + k * 32);
            }
        }
        cp_commit();

        const int n0 = 2 * it;
        const float* Wc0 = Wb + (n0 & 3) * WBUF_FLOATS + j * WS_STRIDE + dq * 4;
        const float* Wc1 = Wb + ((n0 + 1) & 3) * WBUF_FLOATS + j * WS_STRIDE + dq * 4;

        if (pass == 0) {
            ull u2[4][2];
            compute_u(Wc0, xtile, rep, n0, u2);
            #pragma unroll
            for (int bs = 0; bs < 4; ++bs) {
                acc2[bs][0] = f2_add(acc2[bs][0], u2[bs][0]);
                acc2[bs][1] = f2_add(acc2[bs][1], u2[bs][1]);
            }
            compute_u(Wc1, xtile, rep, n0 + 1, u2);
            #pragma unroll
            for (int bs = 0; bs < 4; ++bs) {
                acc2[bs][0] = f2_add(acc2[bs][0], u2[bs][0]);
                acc2[bs][1] = f2_add(acc2[bs][1], u2[bs][1]);
            }
        } else {
            ull uA[4][2], uB[4][2];
            // n0: u_hat + logit partials
            compute_u(Wc0, xtile, rep, n0, uA);
            {
                float4 part;
                float pv[4];
                #pragma unroll
                for (int bs = 0; bs < 4; ++bs) {
                    ull v0 = Vs[((dq * 2 + 0) * BC + rep * 4 + bs) * J_DIM + j];
                    ull v1 = Vs[((dq * 2 + 1) * BC + rep * 4 + bs) * J_DIM + j];
                    pv[bs] = f2_hsum(f2_fma(uA[bs][0], v0, f2_mul(uA[bs][1], v1)));
                }
                part.x = pv[0]; part.y = pv[1]; part.z = pv[2]; part.w = pv[3];
                tbf[(0 * 8 + warp) * 32 + j] = part;
            }
            // n1: u_hat + logit partials
            compute_u(Wc1, xtile, rep, n0 + 1, uB);
            {
                float4 part;
                float pv[4];
                #pragma unroll
                for (int bs = 0; bs < 4; ++bs) {
                    ull v0 = Vs[((dq * 2 + 0) * BC + rep * 4 + bs) * J_DIM + j];
                    ull v1 = Vs[((dq * 2 + 1) * BC + rep * 4 + bs) * J_DIM + j];
                    pv[bs] = f2_hsum(f2_fma(uB[bs][0], v0, f2_mul(uB[bs][1], v1)));
                }
                part.x = pv[0]; part.y = pv[1]; part.z = pv[2]; part.w = pv[3];
                tbf[(1 * 8 + warp) * 32 + j] = part;
            }

            asm volatile("bar.sync %0, 128;" :: "r"(1 + rep) : "memory");

            // batched softmax: 8 interleaved chains (4 bs x 2 n)
            float4 a0 = tbf[(0 * 8 + wg + 0) * 32 + j];
            float4 a1 = tbf[(0 * 8 + wg + 1) * 32 + j];
            float4 a2 = tbf[(0 * 8 + wg + 2) * 32 + j];
            float4 a3 = tbf[(0 * 8 + wg + 3) * 32 + j];
            float4 c0 = tbf[(1 * 8 + wg + 0) * 32 + j];
            float4 c1 = tbf[(1 * 8 + wg + 1) * 32 + j];
            float4 c2v = tbf[(1 * 8 + wg + 2) * 32 + j];
            float4 c3 = tbf[(1 * 8 + wg + 3) * 32 + j];
            // logits are O(1): softmax without max-subtraction is safe here
            float e[8], z[8];
            e[0] = __expf((a0.x + a1.x) + (a2.x + a3.x));
            e[1] = __expf((a0.y + a1.y) + (a2.y + a3.y));
            e[2] = __expf((a0.z + a1.z) + (a2.z + a3.z));
            e[3] = __expf((a0.w + a1.w) + (a2.w + a3.w));
            e[4] = __expf((c0.x + c1.x) + (c2v.x + c3.x));
            e[5] = __expf((c0.y + c1.y) + (c2v.y + c3.y));
            e[6] = __expf((c0.z + c1.z) + (c2v.z + c3.z));
            e[7] = __expf((c0.w + c1.w) + (c2v.w + c3.w));
            #pragma unroll
            for (int k = 0; k < 8; ++k) z[k] = e[k];
            #pragma unroll
            for (int o = 16; o; o >>= 1) {   // 8 interleaved butterflies
                #pragma unroll
                for (int k = 0; k < 8; ++k)
                    z[k] += __shfl_xor_sync(0xffffffffu, z[k], o);
            }
            #pragma unroll
            for (int bs = 0; bs < 4; ++bs) {
                ull cc = f2_dup(__fdividef(e[bs], z[bs]));
                acc2[bs][0] = f2_fma(cc, uA[bs][0], acc2[bs][0]);
                acc2[bs][1] = f2_fma(cc, uA[bs][1], acc2[bs][1]);
                cc = f2_dup(__fdividef(e[4 + bs], z[4 + bs]));
                acc2[bs][0] = f2_fma(cc, uB[bs][0], acc2[bs][0]);
                acc2[bs][1] = f2_fma(cc, uB[bs][1], acc2[bs][1]);
            }
        }
    }

    float* S = g_S[pass];
    #pragma unroll
    for (int bs = 0; bs < 4; ++bs) {
        float* dst = &S[((size_t)(bbase + rep * 4 + bs) * J_DIM + j) * D_DIM + dq * 4];
        float a, b, c, d;
        f2_unpack(acc2[bs][0], a, b);
        f2_unpack(acc2[bs][1], c, d);
        atomicAdd(dst + 0, a);
        atomicAdd(dst + 1, b);
        atomicAdd(dst + 2, c);
        atomicAdd(dst + 3, d);
    }
}

// final squash only: out = squash(S2). idx = (b*32 + j).
__global__ void squash_final_kernel(float* __restrict__ out) {
    int idx = blockIdx.x * blockDim.x + threadIdx.x;
    if (idx >= B_DIM * J_DIM) return;
    const float* S = g_S[2];
    float s[D_DIM];
    float ssq = 0.0f;
#pragma unroll
    for (int d = 0; d < D_DIM; ++d) {
        float v = S[idx * D_DIM + d];
        s[d] = v;
        ssq = fmaf(v, v, ssq);
    }
    float inv = rsqrtf(ssq + 1e-7f);
#pragma unroll
    for (int d = 0; d < D_DIM; ++d) out[idx * D_DIM + d] = s[d] * inv;
}

extern "C" void kernel_launch(void* const* d_in, const int* in_sizes, int n_in,
                              void* d_out, int out_size) {
    const float* x = (const float*)d_in[0];
    const float* W = (const float*)d_in[1];
    // robust to input ordering: x has 64*2048*8 = 1048576 elements
    if (in_sizes[0] != B_DIM * N_DIM * I_DIM) {
        x = (const float*)d_in[1];
        W = (const float*)d_in[0];
    }
    float* out = (float*)d_out;

    cudaFuncSetAttribute(pass_kernel,
                         cudaFuncAttributeMaxDynamicSharedMemorySize, SMEM_BYTES);

    dim3 grid(N_DIM / NC, B_DIM / BC);   // (64, 8) = 512 blocks

    transform_kernel<<<(J_DIM * N_DIM) / 8, 256>>>(W);   // also zeroes g_S
    pass_kernel<<<grid, 256, SMEM_BYTES>>>(x, 0);
    pass_kernel<<<grid, 256, SMEM_BYTES>>>(x, 1);        // squash(S0) fused in prologue
    pass_kernel<<<grid, 256, SMEM_BYTES>>>(x, 2);        // squash(S0)+squash(S1) fused
    squash_final_kernel<<<8, 256>>>(out);
}